// round 4
// baseline (speedup 1.0000x reference)
#include <cuda_runtime.h>
#include <cstdint>
#include <cstddef>

#define SQ 4096
#define NB 64
#define HH 256
#define GC 1024   // 4 gates * 256 units, packed: pcol = j*4 + e  (e: 0=f,1=i,2=o,3=c)

typedef unsigned long long ull;

// ---------------- static device scratch (no allocations allowed) ----------------
__device__ float g_xg[(size_t)SQ * NB * GC];   // 1 GB input projections (+bias)
__device__ float g_Wp[HH * GC];                // packed W_all [k][pcol]
__device__ float g_Up[HH * GC];                // packed U_all [k][pcol]
__device__ float g_bp[GC];                     // packed bias
__device__ float g_h[2][NB * HH];              // double-buffered hidden state
__device__ unsigned g_bar[16];                 // per-group monotonic barrier counters

// ---------------- f32x2 helpers ----------------
__device__ __forceinline__ ull pk2(float x, float y) {
    ull r; asm("mov.b64 %0, {%1, %2};" : "=l"(r) : "f"(x), "f"(y)); return r;
}
__device__ __forceinline__ void fma2(ull& d, ull a, ull b) {
    asm("fma.rn.f32x2 %0, %1, %2, %0;" : "+l"(d) : "l"(a), "l"(b));
}
__device__ __forceinline__ float2 unpk(ull v) {
    float2 r; asm("mov.b64 {%0, %1}, %2;" : "=f"(r.x), "=f"(r.y) : "l"(v)); return r;
}
union F4U2 { float4 f4; ulonglong2 u2; };

__device__ __forceinline__ float sigf(float x) { return 1.0f / (1.0f + expf(-x)); }

// ---------------- phase 0: pack weights, zero state ----------------
__global__ void pack_kernel(const float* __restrict__ Wf, const float* __restrict__ Uf, const float* __restrict__ bf,
                            const float* __restrict__ Wi, const float* __restrict__ Ui, const float* __restrict__ bi,
                            const float* __restrict__ Wc, const float* __restrict__ Uc, const float* __restrict__ bc,
                            const float* __restrict__ Wo, const float* __restrict__ Uo, const float* __restrict__ bo)
{
    int i = blockIdx.x * blockDim.x + threadIdx.x;   // 0 .. 262143
    if (i < HH * GC) {
        int k = i >> 10, p = i & 1023;
        int j = p >> 2, e = p & 3;                   // e: 0=f,1=i,2=o,3=c
        const float* W = (e == 0) ? Wf : (e == 1) ? Wi : (e == 2) ? Wo : Wc;
        const float* U = (e == 0) ? Uf : (e == 1) ? Ui : (e == 2) ? Uo : Uc;
        g_Wp[i] = W[k * HH + j];
        g_Up[i] = U[k * HH + j];
        if (k == 0) {
            const float* B = (e == 0) ? bf : (e == 1) ? bi : (e == 2) ? bo : bc;
            g_bp[p] = B[j];
        }
    }
    if (i < 2 * NB * HH) ((float*)g_h)[i] = 0.0f;
    if (i < 16) g_bar[i] = 0u;
}

// ---------------- phase 1: xg[s*64+b][pcol] = x[b][s][:] @ Wp + bias ----------------
// M = 262144 (m = s*64 + b), N = 1024, K = 256. BM=BN=128, BK=8, 256 thr, 8x8 micro.
__global__ __launch_bounds__(256) void xproj_kernel(const float* __restrict__ x)
{
    __shared__ float As[8][132];   // [k][m], padded
    __shared__ float Bs[8][128];   // [k][n]
    int t  = threadIdx.x;
    int m0 = blockIdx.x * 128;
    int n0 = blockIdx.y * 128;
    int tm = t >> 4, tn = t & 15;

    int arow = t >> 1;
    int akq  = (t & 1) * 4;
    int gm = m0 + arow;
    int bb = gm & 63, ss = gm >> 6;
    const float* aptr = x + ((size_t)bb * SQ + ss) * HH + akq;

    int bkk = t >> 5;
    int bnq = (t & 31) * 4;
    const float* bptr = g_Wp + (size_t)bkk * GC + n0 + bnq;

    ull acc[8][4];
#pragma unroll
    for (int i = 0; i < 8; i++)
#pragma unroll
        for (int j = 0; j < 4; j++) acc[i][j] = 0ull;

    for (int k0 = 0; k0 < HH; k0 += 8) {
        float4 av = *(const float4*)(aptr + k0);
        float4 bv = *(const float4*)(bptr + (size_t)k0 * GC);
        __syncthreads();
        As[akq + 0][arow] = av.x;
        As[akq + 1][arow] = av.y;
        As[akq + 2][arow] = av.z;
        As[akq + 3][arow] = av.w;
        *(float4*)&Bs[bkk][bnq] = bv;
        __syncthreads();
#pragma unroll
        for (int kk = 0; kk < 8; kk++) {
            F4U2 b0, b1;
            float4 a0 = *(const float4*)&As[kk][tm * 8];
            float4 a1 = *(const float4*)&As[kk][tm * 8 + 4];
            b0.f4 = *(const float4*)&Bs[kk][tn * 8];
            b1.f4 = *(const float4*)&Bs[kk][tn * 8 + 4];
            ull bp_[4] = { b0.u2.x, b0.u2.y, b1.u2.x, b1.u2.y };
            float aa[8] = { a0.x, a0.y, a0.z, a0.w, a1.x, a1.y, a1.z, a1.w };
#pragma unroll
            for (int i = 0; i < 8; i++) {
                ull ad = pk2(aa[i], aa[i]);
#pragma unroll
                for (int j = 0; j < 4; j++) fma2(acc[i][j], ad, bp_[j]);
            }
        }
    }

    float4 bi0 = *(const float4*)(g_bp + n0 + tn * 8);
    float4 bi1 = *(const float4*)(g_bp + n0 + tn * 8 + 4);
#pragma unroll
    for (int i = 0; i < 8; i++) {
        float2 v0 = unpk(acc[i][0]), v1 = unpk(acc[i][1]);
        float2 v2 = unpk(acc[i][2]), v3 = unpk(acc[i][3]);
        float* o = g_xg + (size_t)(m0 + tm * 8 + i) * GC + n0 + tn * 8;
        float4 w0 = { v0.x + bi0.x, v0.y + bi0.y, v1.x + bi0.z, v1.y + bi0.w };
        float4 w1 = { v2.x + bi1.x, v2.y + bi1.y, v3.x + bi1.z, v3.y + bi1.w };
        *(float4*)o = w0;
        *(float4*)(o + 4) = w1;
    }
}

// ---------------- phase 2: persistent recurrence ----------------
// 128 CTAs = 16 groups (4 batches each) x 8 column-CTAs (128 pcols = 32 units each).
// SMEM: U slice 128KB + h stage 4KB + reduction 16KB = 151.5KB -> 1 CTA/SM, all resident.
__global__ __launch_bounds__(256) void rnn_kernel()
{
    extern __shared__ float sm[];
    float* smU = sm;                   // [256][128]
    float* smH = sm + HH * 128;        // [256][4]  (k-major, batch fast)
    float* smR = smH + HH * 4;         // [8][4][128] partials

    int t   = threadIdx.x;
    int grp = blockIdx.x >> 3;
    int r   = blockIdx.x & 7;
    int b0  = grp * 4;
    int c0  = r * 128;

    // one-time: load U slice (16x L2 reuse across groups)
    {
        float4* dst = (float4*)smU;
        for (int q = t; q < HH * 32; q += 256) {
            int k = q >> 5, cq = q & 31;
            dst[q] = *(const float4*)(g_Up + (size_t)k * GC + c0 + cq * 4);
        }
    }
    __syncthreads();

    int cg = t & 31, ks = t >> 5;       // GEMM mapping: 4 cols (cg*4..), k-split ks
    int eb = t >> 5, ecq = t & 31;      // epilogue mapping (t<128): batch eb, unit quad ecq
    float C = 0.0f;                      // register-resident cell state (t<128)
    unsigned* barp = &g_bar[grp];

    for (int s = 0; s < SQ; s++) {
        int cur = s & 1;
        if (s > 0) {
            if (t == 0) {
                unsigned target = 8u * (unsigned)s, v;
                do { asm volatile("ld.acquire.gpu.u32 %0, [%1];" : "=r"(v) : "l"(barp)); } while (v < target);
            }
            __syncthreads();
        }

        // prefetch xg for this step (overlaps h load + syncs + GEMM front)
        float4 xg4;
        if (t < 128)
            xg4 = __ldcs((const float4*)(g_xg + ((size_t)s * NB + b0 + eb) * GC + c0 + ecq * 4));

        // stage h (k-major): thread t = k
        {
            const float* hsrc = g_h[cur];
            float4 hv;
            hv.x = __ldcg(hsrc + (b0 + 0) * HH + t);
            hv.y = __ldcg(hsrc + (b0 + 1) * HH + t);
            hv.z = __ldcg(hsrc + (b0 + 2) * HH + t);
            hv.w = __ldcg(hsrc + (b0 + 3) * HH + t);
            *(float4*)&smH[t * 4] = hv;
        }
        __syncthreads();

        // GEMM partials: g[b][c] += sum_{k in my split} h[b][k] * U[k][c]
        ull acc[4][2] = {};
        const float4* U4 = (const float4*)smU;
        const float4* H4 = (const float4*)smH;
        int kbase = ks * 32;
#pragma unroll 8
        for (int kk = 0; kk < 32; kk++) {
            int k = kbase + kk;
            F4U2 u; u.f4 = U4[k * 32 + cg];
            float4 hv = H4[k];
            ull h0 = pk2(hv.x, hv.x), h1 = pk2(hv.y, hv.y);
            ull h2 = pk2(hv.z, hv.z), h3 = pk2(hv.w, hv.w);
            fma2(acc[0][0], h0, u.u2.x); fma2(acc[0][1], h0, u.u2.y);
            fma2(acc[1][0], h1, u.u2.x); fma2(acc[1][1], h1, u.u2.y);
            fma2(acc[2][0], h2, u.u2.x); fma2(acc[2][1], h2, u.u2.y);
            fma2(acc[3][0], h3, u.u2.x); fma2(acc[3][1], h3, u.u2.y);
        }
#pragma unroll
        for (int b = 0; b < 4; b++) {
            float2 p0 = unpk(acc[b][0]), p1 = unpk(acc[b][1]);
            float4 v = { p0.x, p0.y, p1.x, p1.y };
            *(float4*)&smR[((ks * 4) + b) * 128 + cg * 4] = v;
        }
        __syncthreads();

        // reduce + gates + state update (one thread per (batch, hidden unit))
        if (t < 128) {
            float4 g4 = xg4;
#pragma unroll
            for (int q = 0; q < 8; q++) {
                float4 pv = *(const float4*)&smR[((q * 4) + eb) * 128 + ecq * 4];
                g4.x += pv.x; g4.y += pv.y; g4.z += pv.z; g4.w += pv.w;
            }
            float fg = sigf(g4.x);
            float ig = sigf(g4.y);
            float og = sigf(g4.z);
            float cc = sigf(g4.w);     // candidate uses sigmoid (per reference)
            C = fg * C + ig * cc;
            float h = og * tanhf(C);
            __stcg(g_h[cur ^ 1] + (b0 + eb) * HH + r * 32 + ecq, h);
            __threadfence();
        }
        __syncthreads();
        if (t == 0) atomicAdd(barp, 1u);
    }
}

// ---------------- phase 3: out = h_T @ Why + bias_y ----------------
__global__ __launch_bounds__(256) void out_kernel(const float* __restrict__ Why,
                                                  const float* __restrict__ by,
                                                  float* __restrict__ out)
{
    __shared__ float hs[HH];
    int b = blockIdx.x, n = threadIdx.x;
    hs[n] = __ldcg(g_h[0] + b * HH + n);   // final h after 4096 steps lives in buffer 0
    __syncthreads();
    float acc = by[n];
    for (int k = 0; k < HH; k++)
        acc = fmaf(hs[k], Why[(size_t)k * HH + n], acc);
    out[b * HH + n] = acc;
}

// ---------------- launch ----------------
extern "C" void kernel_launch(void* const* d_in, const int* in_sizes, int n_in,
                              void* d_out, int out_size)
{
    (void)in_sizes; (void)n_in; (void)out_size;
    const float* x   = (const float*)d_in[0];
    const float* Wf  = (const float*)d_in[1];
    const float* Uf  = (const float*)d_in[2];
    const float* bf  = (const float*)d_in[3];
    const float* Wi  = (const float*)d_in[4];
    const float* Ui  = (const float*)d_in[5];
    const float* bi  = (const float*)d_in[6];
    const float* Wc  = (const float*)d_in[7];
    const float* Uc  = (const float*)d_in[8];
    const float* bc  = (const float*)d_in[9];
    const float* Wo  = (const float*)d_in[10];
    const float* Uo  = (const float*)d_in[11];
    const float* bo  = (const float*)d_in[12];
    const float* Why = (const float*)d_in[13];
    const float* by  = (const float*)d_in[14];
    float* out = (float*)d_out;

    pack_kernel<<<1024, 256>>>(Wf, Uf, bf, Wi, Ui, bi, Wc, Uc, bc, Wo, Uo, bo);

    dim3 g1(2048, 8);
    xproj_kernel<<<g1, 256>>>(x);

    int smem = (HH * 128 + HH * 4 + 8 * 4 * 128) * (int)sizeof(float);  // 151552 B
    cudaFuncSetAttribute(rnn_kernel, cudaFuncAttributeMaxDynamicSharedMemorySize, smem);
    rnn_kernel<<<128, 256, smem>>>();

    out_kernel<<<64, 256>>>(Why, by, out);
}